// round 13
// baseline (speedup 1.0000x reference)
#include <cuda_runtime.h>
#include <cuda_fp16.h>
#include <math.h>
#include <stdint.h>

#define NN 16384
#define EE 65536
#define GG 128
#define DD 64
#define FIN 64
#define EIN 16
#define HE 64
#define LL 3
#define NSTEPS 3
#define EPSV 1e-5f
#define NCHUNK 65              // 64 hidden k + 1 bias chunk
#define BSTRIDE 72             // padded fp16 row stride (conflict-free LDS)
#define BCH16 (64 * BSTRIDE)   // halfs per chunk image: 4608 (9216 B)

// ---------------- scratch (device globals; no allocation) ----------------
__device__ float d_x[NN * DD];
__device__ float d_agg[NN * DD];
__device__ int   d_cnt[NN];
__device__ float d_invc[NN];
__device__ __align__(16) __half d_Bh[LL * NCHUNK * BCH16];  // fp16 B images

// ---------------- helpers ----------------
__device__ __forceinline__ uint32_t smem_u32(const void* p) {
    return (uint32_t)__cvta_generic_to_shared(p);
}
__device__ __forceinline__ uint32_t packh2(float a, float b) {  // lo=a, hi=b
    uint32_t r;
    asm("cvt.rn.f16x2.f32 %0, %1, %2;" : "=r"(r) : "f"(b), "f"(a));
    return r;
}
__device__ __forceinline__ void hmma(float* c, uint32_t a0, uint32_t a1, uint32_t a2,
                                     uint32_t a3, uint32_t b0, uint32_t b1) {
    asm volatile(
        "mma.sync.aligned.m16n8k16.row.col.f32.f16.f16.f32 "
        "{%0,%1,%2,%3}, {%4,%5,%6,%7}, {%8,%9}, {%0,%1,%2,%3};"
        : "+f"(c[0]), "+f"(c[1]), "+f"(c[2]), "+f"(c[3])
        : "r"(a0), "r"(a1), "r"(a2), "r"(a3), "r"(b0), "r"(b1));
}
#define CP_A16(s, g) asm volatile("cp.async.ca.shared.global [%0], [%1], 16;" :: "r"(s), "l"(g))
#define CP_COMMIT()  asm volatile("cp.async.commit_group;")
#define CP_WAIT1()   asm volatile("cp.async.wait_group 1;")
#define CP_WAIT0()   asm volatile("cp.async.wait_group 0;")

// ---------------- [0] zero cnt + agg ----------------
__global__ void k_zero0() {
    int i = blockIdx.x * blockDim.x + threadIdx.x;
    if (i < NN) d_cnt[i] = 0;
    if (i < NN * DD) d_agg[i] = 0.0f;
}
// ---------------- [1] degree count ----------------
__global__ void k_count(const int* __restrict__ dst) {
    int i = blockIdx.x * blockDim.x + threadIdx.x;
    if (i < EE) atomicAdd(&d_cnt[dst[i]], 1);
}
// ---------------- [2] 1/deg ----------------
__global__ void k_invc() {
    int i = blockIdx.x * blockDim.x + threadIdx.x;
    if (i < NN) d_invc[i] = 1.0f / (float)max(d_cnt[i], 1);
}

// ---------------- [3] lin0: x = relu(x_in @ W + b) ----------------
__global__ __launch_bounds__(256) void k_lin0(const float* __restrict__ xin,
                                              const float* __restrict__ w,
                                              const float* __restrict__ b) {
    __shared__ float ws[FIN * DD];
    __shared__ float xs[4][FIN];
    int t = threadIdx.x;
    for (int i = t; i < FIN * DD; i += 256) ws[i] = w[i];
    int n0 = blockIdx.x * 4;
    {
        int li = t >> 6, d = t & 63;
        xs[li][d] = xin[(size_t)(n0 + li) * FIN + d];
    }
    __syncthreads();
    int li = t >> 6, o = t & 63;
    float acc = b[o];
#pragma unroll
    for (int d = 0; d < FIN; d++) acc += xs[li][d] * ws[d * DD + o];
    d_x[(size_t)(n0 + li) * DD + o] = fmaxf(acc, 0.0f);
}

// ---------------- [4] prep: B chunk images (o-major rows, padded stride, fp16) ----
__global__ void k_prep_B(const float* __restrict__ mw2, const float* __restrict__ mb2) {
    int chunk = blockIdx.x;  // 0 .. LL*NCHUNK-1
    int l = chunk / NCHUNK, kc = chunk % NCHUNK;
    const float* sp = (kc < 64) ? (mw2 + ((size_t)l * 64 + kc) * (DD * DD))
                                : (mb2 + (size_t)l * (DD * DD));
    __half* hb = d_Bh + (size_t)chunk * BCH16;
    for (int i = threadIdx.x; i < DD * DD; i += 256) {
        int d = i >> 6, o = i & 63;  // sp[i] = M[kc][d][o]
        hb[o * BSTRIDE + d] = __float2half_rn(sp[i]);
    }
}

// ---------------- [5,8,11] edge message GEMM (fused h-MLP + single-pass fp16) ----
// Block: 128 edges, 4 warps. Warp tile: 32 edges x 64 outputs.
// Prologue computes h[e,k] for the block's edges into smem (fp16).
// B staged via cp.async double-buffer.
__global__ __launch_bounds__(128) void k_edge_msg_hmma(const int* __restrict__ src,
                                                       const int* __restrict__ dst,
                                                       const float* __restrict__ ea,
                                                       const float* __restrict__ w1,
                                                       const float* __restrict__ b1,
                                                       int layer) {
    __shared__ __half Bs[2][BCH16];        // 18432 B
    __shared__ __half hsm[NCHUNK][128];    // 16640 B

    int t = threadIdx.x, wid = t >> 5, lid = t & 31;
    int g = lid >> 2, tig = lid & 3;
    int e0 = blockIdx.x * 128;

    // ---- stage w1/b1 temporarily in the Bs area ----
    float* wst = (float*)&Bs[0][0];   // 1024 floats
    float* bst = wst + EIN * HE;      // 64 floats
    for (int i = t; i < EIN * HE; i += 128) wst[i] = w1[i];
    if (t < HE) bst[t] = b1[t];

    // ---- this thread's edge-attr row ----
    float ev[EIN];
    {
        const float4* ep = (const float4*)(ea + (size_t)(e0 + t) * EIN);
#pragma unroll
        for (int i = 0; i < 4; i++) {
            float4 v = ep[i];
            ev[4 * i + 0] = v.x; ev[4 * i + 1] = v.y;
            ev[4 * i + 2] = v.z; ev[4 * i + 3] = v.w;
        }
    }
    __syncthreads();

    // ---- h[e,k] = relu(ea @ w1 + b1), fp16 into hsm; two halves of 32 k ----
#pragma unroll
    for (int half = 0; half < 2; half++) {
        float acc[32];
#pragma unroll
        for (int kk = 0; kk < 32; kk++) acc[kk] = bst[half * 32 + kk];
#pragma unroll
        for (int j = 0; j < EIN; j++) {
            float evj = ev[j];
#pragma unroll
            for (int kk = 0; kk < 32; kk++)
                acc[kk] += evj * wst[j * HE + half * 32 + kk];
        }
#pragma unroll
        for (int kk = 0; kk < 32; kk++)
            hsm[half * 32 + kk][t] = __float2half_rn(fmaxf(acc[kk], 0.0f));
    }
    hsm[64][t] = __float2half_rn(1.0f);  // bias chunk

    // ---- y fragments in registers (constant across chunks) ----
    float yv[4][16];
    int edge_id[4];
#pragma unroll
    for (int mt = 0; mt < 2; mt++)
#pragma unroll
        for (int rr = 0; rr < 2; rr++) {
            int e = e0 + wid * 32 + mt * 16 + g + rr * 8;
            edge_id[mt * 2 + rr] = e;
            const float* xr = d_x + (size_t)src[e] * DD;
#pragma unroll
            for (int w = 0; w < 4; w++) {
                float2 v0 = *(const float2*)(xr + w * 16 + tig * 2);
                float2 v1 = *(const float2*)(xr + w * 16 + 8 + tig * 2);
                yv[mt * 2 + rr][w * 4 + 0] = v0.x;
                yv[mt * 2 + rr][w * 4 + 1] = v0.y;
                yv[mt * 2 + rr][w * 4 + 2] = v1.x;
                yv[mt * 2 + rr][w * 4 + 3] = v1.y;
            }
        }

    float acc[2][8][4];
#pragma unroll
    for (int mt = 0; mt < 2; mt++)
#pragma unroll
        for (int nt = 0; nt < 8; nt++)
#pragma unroll
            for (int q = 0; q < 4; q++) acc[mt][nt][q] = 0.0f;

    __syncthreads();  // h done; wst reads complete -> Bs reusable

    const __half* Bh = d_Bh + (size_t)layer * NCHUNK * BCH16;
    uint32_t sB0 = smem_u32(&Bs[0][0]);
    uint32_t sB1 = smem_u32(&Bs[1][0]);

    auto issue_chunk = [&](int kc, int st) {
        const char* gB = (const char*)(Bh + (size_t)kc * BCH16);
        uint32_t sB = st ? sB1 : sB0;
#pragma unroll
        for (int q = 0; q < 4; q++)
            CP_A16(sB + (t + q * 128) * 16, gB + (size_t)(t + q * 128) * 16);
        if (t < 64) CP_A16(sB + (t + 512) * 16, gB + (size_t)(t + 512) * 16);
    };

    issue_chunk(0, 0);
    CP_COMMIT();

    for (int kc = 0; kc < NCHUNK; kc++) {
        int st = kc & 1;
        __syncthreads();
        if (kc + 1 < NCHUNK) {
            issue_chunk(kc + 1, st ^ 1);
            CP_COMMIT();
            CP_WAIT1();
        } else {
            CP_WAIT0();
        }
        __syncthreads();

        float h0  = __half2float(hsm[kc][wid * 32 + g]);
        float h0b = __half2float(hsm[kc][wid * 32 + g + 8]);
        float h1  = __half2float(hsm[kc][wid * 32 + 16 + g]);
        float h1b = __half2float(hsm[kc][wid * 32 + 16 + g + 8]);

#pragma unroll
        for (int w = 0; w < 4; w++) {
            uint32_t ah[2][4];
#pragma unroll
            for (int mt = 0; mt < 2; mt++) {
                float ha = mt ? h1 : h0;
                float hb = mt ? h1b : h0b;
                const float* y0 = yv[mt * 2 + 0];  // row g
                const float* y1 = yv[mt * 2 + 1];  // row g+8
                ah[mt][0] = packh2(ha * y0[w * 4 + 0], ha * y0[w * 4 + 1]);
                ah[mt][1] = packh2(hb * y1[w * 4 + 0], hb * y1[w * 4 + 1]);
                ah[mt][2] = packh2(ha * y0[w * 4 + 2], ha * y0[w * 4 + 3]);
                ah[mt][3] = packh2(hb * y1[w * 4 + 2], hb * y1[w * 4 + 3]);
            }
#pragma unroll
            for (int nt = 0; nt < 8; nt++) {
                int boff = (nt * 8 + g) * BSTRIDE + w * 16 + tig * 2;
                uint32_t b0 = *(const uint32_t*)(&Bs[st][0] + boff);
                uint32_t b1v = *(const uint32_t*)(&Bs[st][0] + boff + 8);
#pragma unroll
                for (int mt = 0; mt < 2; mt++)
                    hmma(acc[mt][nt], ah[mt][0], ah[mt][1], ah[mt][2], ah[mt][3],
                         b0, b1v);
            }
        }
    }

    // ---- scatter: agg[dst] += msg / deg ----
#pragma unroll
    for (int mt = 0; mt < 2; mt++)
#pragma unroll
        for (int rr = 0; rr < 2; rr++) {
            int e = edge_id[mt * 2 + rr];
            int dn = dst[e];
            float ic = d_invc[dn];
            float* p = d_agg + (size_t)dn * DD + tig * 2;
#pragma unroll
            for (int nt = 0; nt < 8; nt++) {
                atomicAdd(&p[nt * 8 + 0], acc[mt][nt][rr * 2 + 0] * ic);
                atomicAdd(&p[nt * 8 + 1], acc[mt][nt][rr * 2 + 1] * ic);
            }
        }
}

// ---------------- root: xc = relu(agg + x @ root_w + b) ----------------
__global__ __launch_bounds__(256) void k_root(const float* __restrict__ w,
                                              const float* __restrict__ b) {
    __shared__ float ws[DD * DD];
    __shared__ float xs[4][DD];
    int t = threadIdx.x;
    for (int i = t; i < DD * DD; i += 256) ws[i] = w[i];
    int n0 = blockIdx.x * 4;
    {
        int li = t >> 6, d = t & 63;
        xs[li][d] = d_x[(size_t)(n0 + li) * DD + d];
    }
    __syncthreads();
    int li = t >> 6, o = t & 63;
    size_t idx = (size_t)(n0 + li) * DD + o;
    float acc = b[o] + d_agg[idx];
#pragma unroll
    for (int d = 0; d < DD; d++) acc += xs[li][d] * ws[d * DD + o];
    d_agg[idx] = fmaxf(acc, 0.0f);
}

// ---------------- GraphNorm + residual; also zeroes agg for next layer ----------
__global__ __launch_bounds__(256) void k_gnorm(const float* __restrict__ gw,
                                               const float* __restrict__ gb,
                                               const float* __restrict__ gs) {
    __shared__ float s[128][DD + 1];
    __shared__ float mean[DD];
    __shared__ float var[DD];
    int g = blockIdx.x, t = threadIdx.x;
    const float* xc = d_agg + (size_t)g * 128 * DD;
    for (int i = t; i < 128 * DD; i += 256) s[i >> 6][i & 63] = xc[i];
    __syncthreads();
    if (t < DD) {
        float m = 0.0f;
        for (int n = 0; n < 128; n++) m += s[n][t];
        mean[t] = m * (1.0f / 128.0f);
    }
    __syncthreads();
    for (int i = t; i < 128 * DD; i += 256) {
        int n = i >> 6, d = i & 63;
        s[n][d] -= gs[d] * mean[d];
    }
    __syncthreads();
    if (t < DD) {
        float v = 0.0f;
        for (int n = 0; n < 128; n++) v += s[n][t] * s[n][t];
        var[t] = v * (1.0f / 128.0f);
    }
    __syncthreads();
    for (int i = t; i < 128 * DD; i += 256) {
        int n = i >> 6, d = i & 63;
        float xn = gw[d] * s[n][d] * rsqrtf(var[d] + EPSV) + gb[d];
        size_t gi = (size_t)g * 128 * DD + i;
        d_x[gi] = xn + d_x[gi];
        d_agg[gi] = 0.0f;  // ready for next layer's scatter
    }
}

// ---------------- Set2Set (3 steps) + head, one block per graph ----------------
__global__ __launch_bounds__(128) void k_s2s(const float* __restrict__ wih,
                                             const float* __restrict__ whh,
                                             const float* __restrict__ bih,
                                             const float* __restrict__ bhh,
                                             const float* __restrict__ hw1,
                                             const float* __restrict__ hb1,
                                             const float* __restrict__ hw2,
                                             const float* __restrict__ hb2,
                                             float* __restrict__ out) {
    __shared__ float sx[128][DD + 1];
    __shared__ float q_star[2 * DD];
    __shared__ float sh[DD], sc[DD];
    __shared__ float gates[4 * DD];
    __shared__ float red[128];
    __shared__ float sa[128];
    __shared__ float sr[DD];
    int g = blockIdx.x, t = threadIdx.x;
    const float* xg = d_x + (size_t)g * 128 * DD;
    for (int i = t; i < 128 * DD; i += 128) sx[i >> 6][i & 63] = xg[i];
    q_star[t] = 0.0f;
    if (t < DD) { sh[t] = 0.0f; sc[t] = 0.0f; }
    __syncthreads();

    for (int step = 0; step < NSTEPS; step++) {
#pragma unroll
        for (int rr = 0; rr < 2; rr++) {
            int r = t + rr * 128;
            float acc = bih[r] + bhh[r];
            const float* wr = wih + (size_t)r * (2 * DD);
            for (int j = 0; j < 2 * DD; j++) acc += q_star[j] * wr[j];
            const float* vr = whh + (size_t)r * DD;
            for (int j = 0; j < DD; j++) acc += sh[j] * vr[j];
            gates[r] = acc;
        }
        __syncthreads();
        if (t < DD) {
            float ig = 1.0f / (1.0f + expf(-gates[t]));
            float fg = 1.0f / (1.0f + expf(-gates[DD + t]));
            float gg = tanhf(gates[2 * DD + t]);
            float og = 1.0f / (1.0f + expf(-gates[3 * DD + t]));
            float c = fg * sc[t] + ig * gg;
            sc[t] = c;
            sh[t] = og * tanhf(c);
        }
        __syncthreads();
        float ee = 0.0f;
#pragma unroll
        for (int d = 0; d < DD; d++) ee += sx[t][d] * sh[d];
        red[t] = ee;
        __syncthreads();
        for (int off = 64; off; off >>= 1) {
            if (t < off) red[t] = fmaxf(red[t], red[t + off]);
            __syncthreads();
        }
        float emax = red[0];
        __syncthreads();
        float ex = expf(ee - emax);
        red[t] = ex;
        __syncthreads();
        for (int off = 64; off; off >>= 1) {
            if (t < off) red[t] += red[t + off];
            __syncthreads();
        }
        float denom = red[0];
        sa[t] = ex / denom;
        __syncthreads();
        if (t < DD) {
            float r = 0.0f;
            for (int n = 0; n < 128; n++) r += sa[n] * sx[n][t];
            sr[t] = r;
        }
        __syncthreads();
        q_star[t] = (t < DD) ? sh[t] : sr[t - DD];
        __syncthreads();
    }
    if (t < DD) {
        float acc = hb1[t];
        for (int j = 0; j < 2 * DD; j++) acc += q_star[j] * hw1[j * DD + t];
        red[t] = fmaxf(acc, 0.0f) * hw2[t];
    }
    __syncthreads();
    if (t < 32) {
        float v = red[t] + red[t + 32];
        for (int off = 16; off; off >>= 1) v += __shfl_down_sync(0xffffffffu, v, off);
        if (t == 0) out[g] = v + hb2[0];
    }
}

// ---------------- launch ----------------
extern "C" void kernel_launch(void* const* d_in, const int* in_sizes, int n_in,
                              void* d_out, int out_size) {
    const float* x     = (const float*)d_in[0];
    const int*   ei    = (const int*)d_in[1];
    const float* ea    = (const float*)d_in[2];
    const float* lin0w = (const float*)d_in[4];
    const float* lin0b = (const float*)d_in[5];
    const float* mw1   = (const float*)d_in[6];
    const float* mb1   = (const float*)d_in[7];
    const float* mw2   = (const float*)d_in[8];
    const float* mb2   = (const float*)d_in[9];
    const float* rootw = (const float*)d_in[10];
    const float* convb = (const float*)d_in[11];
    const float* gnw   = (const float*)d_in[12];
    const float* gnb   = (const float*)d_in[13];
    const float* gns   = (const float*)d_in[14];
    const float* wih   = (const float*)d_in[15];
    const float* whh   = (const float*)d_in[16];
    const float* bih   = (const float*)d_in[17];
    const float* bhh   = (const float*)d_in[18];
    const float* hw1   = (const float*)d_in[19];
    const float* hb1   = (const float*)d_in[20];
    const float* hw2   = (const float*)d_in[21];
    const float* hb2   = (const float*)d_in[22];
    float* out = (float*)d_out;

    const int* src = ei;
    const int* dst = ei + EE;

    k_zero0<<<(NN * DD) / 256, 256>>>();                          // [0]
    k_count<<<EE / 256, 256>>>(dst);                              // [1]
    k_invc<<<NN / 256, 256>>>();                                  // [2]
    k_lin0<<<NN / 4, 256>>>(x, lin0w, lin0b);                     // [3]
    k_prep_B<<<LL * NCHUNK, 256>>>(mw2, mb2);                     // [4]

    for (int l = 0; l < LL; l++) {
        k_edge_msg_hmma<<<EE / 128, 128>>>(src, dst, ea,
                                           mw1 + (size_t)l * EIN * HE,
                                           mb1 + (size_t)l * HE, l);   // [5],[8],[11]
        k_root<<<NN / 4, 256>>>(rootw + (size_t)l * DD * DD, convb + (size_t)l * DD);
        k_gnorm<<<GG, 256>>>(gnw + (size_t)l * DD, gnb + (size_t)l * DD, gns + (size_t)l * DD);
    }

    k_s2s<<<GG, 128>>>(wih, whh, bih, bhh, hw1, hb1, hw2, hb2, out);  // [14]
}